// round 1
// baseline (speedup 1.0000x reference)
#include <cuda_runtime.h>

// ---------------------------------------------------------------------------
// Groupwise CNN + 32 independent 2-layer LSTMs + gaussian head
//   x:[128,128,128] -> grouped conv1d(k=3,p=1, 1->16 per group) -> relu
//   -> maxpool(k2 s2 p1) -> [B,128,16*65] -> fc1 -> z:[B,128,32]
//   -> per-feature 2-layer LSTM over t=0..127 -> h_top:[B,32,32]
//   -> mu / logvar heads -> (mu-1.96s, mu, mu+1.96s, logvar)
// ---------------------------------------------------------------------------

typedef unsigned long long ull;

#define B_    128
#define W_    128
#define NF_   128
#define KC_   16
#define POOL_ 65
#define FC1_  32
#define H_    32

// scratch (allocation-free rule: __device__ globals)
__device__ float g_z[B_ * W_ * FC1_];        // [b][t][f]
__device__ float g_comb[B_ * FC1_ * H_];     // [b][f*32+h]

__device__ __forceinline__ void ffma2(ull &d, ull a, ull b) {
    asm("fma.rn.f32x2 %0, %1, %2, %0;" : "+l"(d) : "l"(a), "l"(b));
}
__device__ __forceinline__ float redu(ull a) {
    float lo, hi;
    asm("mov.b64 {%0,%1}, %2;" : "=f"(lo), "=f"(hi) : "l"(a));
    return lo + hi;
}
__device__ __forceinline__ ull pk2(float lo, float hi) {
    ull r;
    asm("mov.b64 %0, {%1,%2};" : "=l"(r) : "f"(lo), "f"(hi));
    return r;
}
__device__ __forceinline__ float sigmf(float x) {
    return __fdividef(1.0f, 1.0f + __expf(-x));
}
__device__ __forceinline__ float tanhfa(float x) {
    // 2/(1+e^{-2x}) - 1 : safe at both saturations (inf -> -1, 0 -> +1)
    return __fdividef(2.0f, 1.0f + __expf(-2.0f * x)) - 1.0f;
}

// ---------------------------------------------------------------------------
// Kernel 1: per-batch fused conv -> relu -> maxpool -> fc1.
// One block per b; fc1_w (133KB) cached in smem, reused across all 128 w-rows.
// ---------------------------------------------------------------------------
__global__ __launch_bounds__(256) void k_convfc(
    const float* __restrict__ x,
    const float* __restrict__ conv_w, const float* __restrict__ conv_b,
    const float* __restrict__ fc1_w,  const float* __restrict__ fc1_b)
{
    extern __shared__ float sm1[];
    float* Wf     = sm1;            // 33280 floats (32 x 1040)
    float* pooled = Wf + 33280;     // 1040
    float* xr     = pooled + 1040;  // 132  (padded x row: [0]=0, [1..128]=x, [129]=0)
    float* cw     = xr + 132;       // 48   (16 kernels x 3 taps)
    float* cb     = cw + 48;        // 16
    float* fb     = cb + 16;        // 32

    const int tid = threadIdx.x;
    const int b   = blockIdx.x;

    for (int i = tid; i < 33280; i += 256) Wf[i] = fc1_w[i];
    if (tid < 32)  fb[tid] = fc1_b[tid];
    if (tid == 32) { xr[0] = 0.0f; xr[129] = 0.0f; }

    const ull* Wfu = (const ull*)Wf;
    const ull* pu  = (const ull*)pooled;
    const int  wg  = tid >> 5, lane = tid & 31;
    __syncthreads();

    for (int w = 0; w < W_; ++w) {
        if (tid < 128)                   xr[tid + 1]   = x[b * 16384 + w * 128 + tid];
        if (tid >= 128 && tid < 176)     cw[tid - 128] = conv_w[w * 48 + (tid - 128)];
        if (tid >= 176 && tid < 192)     cb[tid - 176] = conv_b[w * 16 + (tid - 176)];
        __syncthreads();

        // pooled[k*65+j] = max(relu(conv at 2j-1), relu(conv at 2j))  (-inf pads)
        for (int idx = tid; idx < 1040; idx += 256) {
            int k = idx / 65;
            int j = idx - k * 65;
            float c0w = cw[k * 3], c1w = cw[k * 3 + 1], c2w = cw[k * 3 + 2], bb = cb[k];
            float va = -1e30f, vb = -1e30f;
            int p = 2 * j;
            if (p > 0)
                va = fmaxf(0.0f, bb + c0w * xr[p - 1] + c1w * xr[p]     + c2w * xr[p + 1]);
            if (p < 128)
                vb = fmaxf(0.0f, bb + c0w * xr[p]     + c1w * xr[p + 1] + c2w * xr[p + 2]);
            pooled[idx] = fmaxf(va, vb);
        }
        __syncthreads();

        // fc1: warp wg computes outputs [4wg .. 4wg+3] via packed-f32x2 dot
        ull a0 = 0, a1 = 0, a2 = 0, a3 = 0;
        const int ob = wg * 4;
        for (int i2 = lane; i2 < 520; i2 += 32) {
            ull pv = pu[i2];
            ffma2(a0, pv, Wfu[(ob + 0) * 520 + i2]);
            ffma2(a1, pv, Wfu[(ob + 1) * 520 + i2]);
            ffma2(a2, pv, Wfu[(ob + 2) * 520 + i2]);
            ffma2(a3, pv, Wfu[(ob + 3) * 520 + i2]);
        }
        float r0 = redu(a0), r1 = redu(a1), r2 = redu(a2), r3 = redu(a3);
        #pragma unroll
        for (int s = 16; s > 0; s >>= 1) {
            r0 += __shfl_xor_sync(0xffffffffu, r0, s);
            r1 += __shfl_xor_sync(0xffffffffu, r1, s);
            r2 += __shfl_xor_sync(0xffffffffu, r2, s);
            r3 += __shfl_xor_sync(0xffffffffu, r3, s);
        }
        if (lane == 0) {
            float* zp = g_z + b * 4096 + w * 32 + ob;
            zp[0] = r0 + fb[ob];
            zp[1] = r1 + fb[ob + 1];
            zp[2] = r2 + fb[ob + 2];
            zp[3] = r3 + fb[ob + 3];
        }
        __syncthreads();
    }
}

// ---------------------------------------------------------------------------
// Kernel 2: the LSTM. Block = (f, 32-batch chunk), 256 threads.
// warp <-> 4 cells; lane = hidden index (owns gates lane,+32,+64,+96 = i,f,g,o
// of hidden unit `lane`): zero cross-lane traffic in the cell update.
// No __syncthreads in the 128-step loop; h flows through per-warp smem rows.
// All weights packed as f32x2 pairs over the h (contraction) axis.
// ---------------------------------------------------------------------------
__global__ __launch_bounds__(256) void k_lstm(
    const float* __restrict__ w_ih0, const float* __restrict__ w_ih1,
    const float* __restrict__ w_hh,  const float* __restrict__ b_lstm)
{
    extern __shared__ ull sm2[];
    ull*   W0   = sm2;              // [16 hp][128 g]  layer0 w_hh pairs (16KB)
    ull*   Wc   = W0 + 2048;        // [32 hp][128 g]  layer1 [w_ih1 ; w_hh1] (32KB)
    ull*   hcat = Wc + 4096;        // [32 b][32 pairs] = per-b 64 floats: h0|h1 (8KB)
    float* zb   = (float*)(hcat + 1024);  // [32 b][128 t] (16KB)
    float* wi0  = zb + 4096;        // 128
    float* bs0  = wi0 + 128;        // 128
    float* bs1  = bs0 + 128;        // 128

    const int tid = threadIdx.x;
    const int f   = blockIdx.x & 31;
    const int b0  = (blockIdx.x >> 5) * 32;

    const float* whh0 = w_hh  + (size_t)f        * 4096;  // [g][h]
    const float* whh1 = w_hh  + (size_t)(32 + f) * 4096;
    const float* wi1  = w_ih1 + (size_t)f        * 4096;

    for (int idx = tid; idx < 2048; idx += 256) {
        int hp = idx >> 7, g = idx & 127;
        float2 v = *(const float2*)(whh0 + g * 32 + 2 * hp);
        W0[idx] = pk2(v.x, v.y);
    }
    for (int idx = tid; idx < 4096; idx += 256) {
        int hp = idx >> 7, g = idx & 127;
        float2 v;
        if (hp < 16) v = *(const float2*)(wi1  + g * 32 + 2 * hp);
        else         v = *(const float2*)(whh1 + g * 32 + (2 * hp - 32));
        Wc[idx] = pk2(v.x, v.y);
    }
    if (tid < 128) {
        wi0[tid] = w_ih0[f * 128 + tid];
        bs0[tid] = b_lstm[f * 128 + tid];
        bs1[tid] = b_lstm[(32 + f) * 128 + tid];
    }
    for (int idx = tid; idx < 4096; idx += 256) {
        int bl = idx >> 7, t = idx & 127;
        zb[idx] = g_z[(size_t)(b0 + bl) * 4096 + t * 32 + f];
    }
    for (int idx = tid; idx < 1024; idx += 256) hcat[idx] = 0ull;
    __syncthreads();

    const int wg = tid >> 5, lane = tid & 31;
    float c0[4]  = {0, 0, 0, 0};
    float c1[4]  = {0, 0, 0, 0};
    float h1v[4] = {0, 0, 0, 0};
    ull* hb[4];
    #pragma unroll
    for (int r = 0; r < 4; ++r) hb[r] = hcat + (wg * 4 + r) * 32;

    for (int t = 0; t < 128; ++t) {
        // ---- layer 0: gates = x_t*w_ih0 + h0_prev @ w_hh0 + b0
        ull a[4][4];
        #pragma unroll
        for (int r = 0; r < 4; ++r) { a[r][0] = 0; a[r][1] = 0; a[r][2] = 0; a[r][3] = 0; }
        #pragma unroll
        for (int hp = 0; hp < 16; ++hp) {
            ull w0 = W0[hp * 128 + lane];
            ull w1 = W0[hp * 128 + lane + 32];
            ull w2 = W0[hp * 128 + lane + 64];
            ull w3 = W0[hp * 128 + lane + 96];
            #pragma unroll
            for (int r = 0; r < 4; ++r) {
                ull hv = hb[r][hp];
                ffma2(a[r][0], hv, w0);
                ffma2(a[r][1], hv, w1);
                ffma2(a[r][2], hv, w2);
                ffma2(a[r][3], hv, w3);
            }
        }
        float h0v[4];
        #pragma unroll
        for (int r = 0; r < 4; ++r) {
            float xv = zb[(wg * 4 + r) * 128 + t];
            float gi = redu(a[r][0]) + bs0[lane]      + xv * wi0[lane];
            float gf = redu(a[r][1]) + bs0[lane + 32] + xv * wi0[lane + 32];
            float gg = redu(a[r][2]) + bs0[lane + 64] + xv * wi0[lane + 64];
            float go = redu(a[r][3]) + bs0[lane + 96] + xv * wi0[lane + 96];
            c0[r]  = sigmf(gf) * c0[r] + sigmf(gi) * tanhfa(gg);
            h0v[r] = sigmf(go) * tanhfa(c0[r]);
        }
        __syncwarp();
        #pragma unroll
        for (int r = 0; r < 4; ++r) ((float*)hb[r])[lane] = h0v[r];
        __syncwarp();

        // ---- layer 1: gates = [h0_new ; h1_prev] @ [w_ih1 ; w_hh1] + b1
        #pragma unroll
        for (int r = 0; r < 4; ++r) { a[r][0] = 0; a[r][1] = 0; a[r][2] = 0; a[r][3] = 0; }
        #pragma unroll
        for (int hp = 0; hp < 32; ++hp) {
            ull w0 = Wc[hp * 128 + lane];
            ull w1 = Wc[hp * 128 + lane + 32];
            ull w2 = Wc[hp * 128 + lane + 64];
            ull w3 = Wc[hp * 128 + lane + 96];
            #pragma unroll
            for (int r = 0; r < 4; ++r) {
                ull hv = hb[r][hp];
                ffma2(a[r][0], hv, w0);
                ffma2(a[r][1], hv, w1);
                ffma2(a[r][2], hv, w2);
                ffma2(a[r][3], hv, w3);
            }
        }
        #pragma unroll
        for (int r = 0; r < 4; ++r) {
            float gi = redu(a[r][0]) + bs1[lane];
            float gf = redu(a[r][1]) + bs1[lane + 32];
            float gg = redu(a[r][2]) + bs1[lane + 64];
            float go = redu(a[r][3]) + bs1[lane + 96];
            c1[r]  = sigmf(gf) * c1[r] + sigmf(gi) * tanhfa(gg);
            h1v[r] = sigmf(go) * tanhfa(c1[r]);
        }
        __syncwarp();
        #pragma unroll
        for (int r = 0; r < 4; ++r) ((float*)hb[r])[32 + lane] = h1v[r];
        __syncwarp();
    }

    #pragma unroll
    for (int r = 0; r < 4; ++r)
        g_comb[(size_t)(b0 + wg * 4 + r) * 1024 + f * 32 + lane] = h1v[r];
}

// ---------------------------------------------------------------------------
// Kernel 3: gaussian head. Block per b.
// ---------------------------------------------------------------------------
__global__ __launch_bounds__(128) void k_head(
    const float* __restrict__ mu_w, const float* __restrict__ mu_b,
    const float* __restrict__ lv_w, const float* __restrict__ lv_b,
    float* __restrict__ out)
{
    __shared__ float smu[4], slv[4];
    const int tid = threadIdx.x, b = blockIdx.x;
    float am = 0.0f, al = 0.0f;
    for (int i = tid; i < 1024; i += 128) {
        float v = g_comb[(size_t)b * 1024 + i];
        am += v * mu_w[i];
        al += v * lv_w[i];
    }
    #pragma unroll
    for (int s = 16; s > 0; s >>= 1) {
        am += __shfl_xor_sync(0xffffffffu, am, s);
        al += __shfl_xor_sync(0xffffffffu, al, s);
    }
    const int wg = tid >> 5, lane = tid & 31;
    if (lane == 0) { smu[wg] = am; slv[wg] = al; }
    __syncthreads();
    if (tid == 0) {
        float mu = smu[0] + smu[1] + smu[2] + smu[3] + mu_b[0];
        float lv = slv[0] + slv[1] + slv[2] + slv[3] + lv_b[0];
        float sg = expf(0.5f * lv);
        out[b]       = mu - 1.96f * sg;
        out[128 + b] = mu;
        out[256 + b] = mu + 1.96f * sg;
        out[384 + b] = lv;
    }
}

// ---------------------------------------------------------------------------
extern "C" void kernel_launch(void* const* d_in, const int* in_sizes, int n_in,
                              void* d_out, int out_size)
{
    const float* x      = (const float*)d_in[0];
    const float* conv_w = (const float*)d_in[1];
    const float* conv_b = (const float*)d_in[2];
    const float* fc1_w  = (const float*)d_in[3];
    const float* fc1_b  = (const float*)d_in[4];
    const float* w_ih0  = (const float*)d_in[5];
    const float* w_ih1  = (const float*)d_in[6];
    const float* w_hh   = (const float*)d_in[7];
    const float* b_lstm = (const float*)d_in[8];
    const float* mu_w   = (const float*)d_in[9];
    const float* mu_b   = (const float*)d_in[10];
    const float* lv_w   = (const float*)d_in[11];
    const float* lv_b   = (const float*)d_in[12];
    float* out = (float*)d_out;

    const int SM1 = (33280 + 1040 + 132 + 48 + 16 + 32) * (int)sizeof(float);   // 138,192 B
    const int SM2 = (2048 + 4096 + 1024) * (int)sizeof(ull)
                  + (4096 + 384) * (int)sizeof(float);                           //  75,264 B

    cudaFuncSetAttribute(k_convfc, cudaFuncAttributeMaxDynamicSharedMemorySize, SM1);
    cudaFuncSetAttribute(k_lstm,   cudaFuncAttributeMaxDynamicSharedMemorySize, SM2);

    k_convfc<<<128, 256, SM1>>>(x, conv_w, conv_b, fc1_w, fc1_b);
    k_lstm<<<128, 256, SM2>>>(w_ih0, w_ih1, w_hh, b_lstm);
    k_head<<<128, 128>>>(mu_w, mu_b, lv_w, lv_b, out);
}

// round 2
// speedup vs baseline: 1.2562x; 1.2562x over previous
#include <cuda_runtime.h>

// ---------------------------------------------------------------------------
// Groupwise CNN + 32 independent 2-layer LSTMs + gaussian head
// ---------------------------------------------------------------------------

typedef unsigned long long ull;

#define B_    128
#define W_    128
#define FC1_  32
#define H_    32

// scratch (allocation-free rule: __device__ globals)
__device__ float g_z[B_ * W_ * FC1_];        // [b][t][f]
__device__ float g_comb[B_ * FC1_ * H_];     // [b][f*32+h]

__device__ __forceinline__ void ffma2(ull &d, ull a, ull b) {
    asm("fma.rn.f32x2 %0, %1, %2, %0;" : "+l"(d) : "l"(a), "l"(b));
}
__device__ __forceinline__ float redu(ull a) {
    float lo, hi;
    asm("mov.b64 {%0,%1}, %2;" : "=f"(lo), "=f"(hi) : "l"(a));
    return lo + hi;
}
__device__ __forceinline__ ull pk2(float lo, float hi) {
    ull r;
    asm("mov.b64 %0, {%1,%2};" : "=l"(r) : "f"(lo), "f"(hi));
    return r;
}
__device__ __forceinline__ float sigmf(float x) {
    return __fdividef(1.0f, 1.0f + __expf(-x));
}
__device__ __forceinline__ float tanhfa(float x) {
    return __fdividef(2.0f, 1.0f + __expf(-2.0f * x)) - 1.0f;
}

// ---------------------------------------------------------------------------
// Kernel 1: per-batch fused conv -> relu -> maxpool -> fc1.
// 512 threads, 8 phases of 16 w-rows. fc1_w cached in smem (row-padded to
// 521 pairs for conflict-free LDS.64). GEMM: warp = (K-chunk, 4-w-row group),
// lane = output o; per-thread 4 accumulators; smem combine of 4 K-chunks.
// ---------------------------------------------------------------------------
__global__ __launch_bounds__(512) void k_convfc(
    const float* __restrict__ x,
    const float* __restrict__ conv_w, const float* __restrict__ conv_b,
    const float* __restrict__ fc1_w,  const float* __restrict__ fc1_b)
{
    extern __shared__ float sm1[];
    float* Wfp    = sm1;            // 32 x 1042 = 33344 floats (pad: 521 pairs/row)
    float* pooled = Wfp + 33344;    // 16 x 1040 = 16640
    float* part   = pooled + 16640; // 16 wid x 4 r x 32 o = 2048
    float* xr     = part + 2048;    // 16 x 132 = 2112
    float* cw     = xr + 2112;      // 768
    float* cb     = cw + 768;       // 256
    float* fb     = cb + 256;       // 32

    const int tid = threadIdx.x;
    const int b   = blockIdx.x;

    // load fc1 weights (padded rows) + bias
    for (int o = 0; o < 32; ++o)
        for (int c = tid; c < 1040; c += 512)
            Wfp[o * 1042 + c] = fc1_w[o * 1040 + c];
    if (tid < 32) fb[tid] = fc1_b[tid];

    const int wid  = tid >> 5, lane = tid & 31;
    const int cch  = wid >> 2;            // K-chunk 0..3 (130 pairs each)
    const int g    = wid & 3;             // w-row group 0..3 (4 rows each)
    const int i2b  = cch * 130;

    for (int ph = 0; ph < 8; ++ph) {
        const int w0 = ph * 16;
        __syncthreads();
        // load x rows + conv params for 16 w
        for (int idx = tid; idx < 2048; idx += 512) {
            int row = idx >> 7, col = idx & 127;
            xr[row * 132 + col + 1] = x[b * 16384 + (w0 + row) * 128 + col];
        }
        if (tid < 16) { xr[tid * 132] = 0.0f; xr[tid * 132 + 129] = 0.0f; }
        for (int idx = tid; idx < 768; idx += 512) cw[idx] = conv_w[w0 * 48 + idx];
        if (tid < 256) cb[tid] = conv_b[w0 * 16 + tid];
        __syncthreads();

        // conv + relu + maxpool for 16 rows
        for (int idx = tid; idx < 16640; idx += 512) {
            int row = idx / 1040;
            int rem = idx - row * 1040;
            int k   = rem / 65;
            int j   = rem - k * 65;
            float c0w = cw[row * 48 + k * 3];
            float c1w = cw[row * 48 + k * 3 + 1];
            float c2w = cw[row * 48 + k * 3 + 2];
            float bb  = cb[row * 16 + k];
            const float* xp = xr + row * 132;
            float va = -1e30f, vb = -1e30f;
            int p = 2 * j;
            if (p > 0)
                va = fmaxf(0.0f, bb + c0w * xp[p - 1] + c1w * xp[p]     + c2w * xp[p + 1]);
            if (p < 128)
                vb = fmaxf(0.0f, bb + c0w * xp[p]     + c1w * xp[p + 1] + c2w * xp[p + 2]);
            pooled[idx] = fmaxf(va, vb);
        }
        __syncthreads();

        // GEMM: thread computes (4 w-rows of group g) x (output lane) over K-chunk
        {
            const ull* wrow = (const ull*)Wfp + lane * 521 + i2b;
            const ull* p0   = (const ull*)pooled + (g * 4 + 0) * 520 + i2b;
            const ull* p1   = (const ull*)pooled + (g * 4 + 1) * 520 + i2b;
            const ull* p2   = (const ull*)pooled + (g * 4 + 2) * 520 + i2b;
            const ull* p3   = (const ull*)pooled + (g * 4 + 3) * 520 + i2b;
            ull a0 = 0, a1 = 0, a2 = 0, a3 = 0;
            #pragma unroll 2
            for (int i2 = 0; i2 < 130; ++i2) {
                ull wv = wrow[i2];
                ffma2(a0, p0[i2], wv);
                ffma2(a1, p1[i2], wv);
                ffma2(a2, p2[i2], wv);
                ffma2(a3, p3[i2], wv);
            }
            part[(wid * 4 + 0) * 32 + lane] = redu(a0);
            part[(wid * 4 + 1) * 32 + lane] = redu(a1);
            part[(wid * 4 + 2) * 32 + lane] = redu(a2);
            part[(wid * 4 + 3) * 32 + lane] = redu(a3);
        }
        __syncthreads();

        // combine 4 K-chunks + bias, write z
        {
            int w_l = tid >> 5, o = tid & 31;
            int gg = w_l >> 2, rr = w_l & 3;
            float s = fb[o];
            #pragma unroll
            for (int c = 0; c < 4; ++c)
                s += part[((c * 4 + gg) * 4 + rr) * 32 + o];
            g_z[b * 4096 + (w0 + w_l) * 32 + o] = s;
        }
    }
}

// ---------------------------------------------------------------------------
// Kernel 2: the LSTM. Block = (f, 32-batch chunk), 256 threads.
// warp <-> 4 cells; lane = hidden index (owns gates lane,+32,+64,+96).
// Weights packed as ulonglong2 (4 floats) -> LDS.128 feeds 4 ffma2.
// Bias + x*w_ih0 folded into accumulator init. No __syncthreads in the loop.
// ---------------------------------------------------------------------------
__global__ __launch_bounds__(256) void k_lstm(
    const float* __restrict__ w_ih0, const float* __restrict__ w_ih1,
    const float* __restrict__ w_hh,  const float* __restrict__ b_lstm)
{
    extern __shared__ ull sm2[];
    ulonglong2* W0q = (ulonglong2*)sm2;            // [8 hp2][128 g]   16KB
    ulonglong2* Wcq = (ulonglong2*)(sm2 + 2048);   // [16 hp2][128 g]  32KB
    ull*   hcat = sm2 + 6144;                      // [32 b][32 pairs]  8KB
    float* zb   = (float*)(sm2 + 7168);            // [32 b][128 t]    16KB
    float* wi0  = zb + 4096;                       // 128
    float* bs0  = wi0 + 128;                       // 128
    float* bs1  = bs0 + 128;                       // 128

    const int tid = threadIdx.x;
    const int f   = blockIdx.x & 31;
    const int b0  = (blockIdx.x >> 5) * 32;

    const float* whh0 = w_hh  + (size_t)f        * 4096;  // [g][h]
    const float* whh1 = w_hh  + (size_t)(32 + f) * 4096;
    const float* wi1  = w_ih1 + (size_t)f        * 4096;

    for (int idx = tid; idx < 1024; idx += 256) {
        int hp2 = idx >> 7, gg = idx & 127;
        float4 v = *(const float4*)(whh0 + gg * 32 + 4 * hp2);
        W0q[idx] = make_ulonglong2(pk2(v.x, v.y), pk2(v.z, v.w));
    }
    for (int idx = tid; idx < 2048; idx += 256) {
        int hp2 = idx >> 7, gg = idx & 127;
        float4 v = (hp2 < 8) ? *(const float4*)(wi1  + gg * 32 + 4 * hp2)
                             : *(const float4*)(whh1 + gg * 32 + 4 * (hp2 - 8));
        Wcq[idx] = make_ulonglong2(pk2(v.x, v.y), pk2(v.z, v.w));
    }
    if (tid < 128) {
        wi0[tid] = w_ih0[f * 128 + tid];
        bs0[tid] = b_lstm[f * 128 + tid];
        bs1[tid] = b_lstm[(32 + f) * 128 + tid];
    }
    for (int idx = tid; idx < 4096; idx += 256) {
        int bl = idx >> 7, t = idx & 127;
        zb[idx] = g_z[(size_t)(b0 + bl) * 4096 + t * 32 + f];
    }
    for (int idx = tid; idx < 1024; idx += 256) hcat[idx] = 0ull;
    __syncthreads();

    const int wg = tid >> 5, lane = tid & 31;

    // per-lane hoisted scalars
    float wi0g[4], bs0g[4];
    ull   binit1[4];
    #pragma unroll
    for (int gg = 0; gg < 4; ++gg) {
        wi0g[gg]   = wi0[lane + 32 * gg];
        bs0g[gg]   = bs0[lane + 32 * gg];
        binit1[gg] = pk2(bs1[lane + 32 * gg], 0.0f);
    }

    float c0[4]  = {0, 0, 0, 0};
    float c1[4]  = {0, 0, 0, 0};
    float h1v[4] = {0, 0, 0, 0};
    ull* hb[4];
    const float* zrow[4];
    #pragma unroll
    for (int r = 0; r < 4; ++r) {
        hb[r]   = hcat + (wg * 4 + r) * 32;
        zrow[r] = zb + (wg * 4 + r) * 128;
    }

    for (int t = 0; t < 128; ++t) {
        // ---- layer 0 ----
        ull a[4][4];
        #pragma unroll
        for (int r = 0; r < 4; ++r) {
            float xv = zrow[r][t];
            #pragma unroll
            for (int gg = 0; gg < 4; ++gg)
                a[r][gg] = pk2(fmaf(xv, wi0g[gg], bs0g[gg]), 0.0f);
        }
        #pragma unroll
        for (int hp2 = 0; hp2 < 8; ++hp2) {
            ulonglong2 w0 = W0q[hp2 * 128 + lane];
            ulonglong2 w1 = W0q[hp2 * 128 + lane + 32];
            ulonglong2 w2 = W0q[hp2 * 128 + lane + 64];
            ulonglong2 w3 = W0q[hp2 * 128 + lane + 96];
            #pragma unroll
            for (int r = 0; r < 4; ++r) {
                ulonglong2 hv = ((const ulonglong2*)hb[r])[hp2];
                ffma2(a[r][0], hv.x, w0.x); ffma2(a[r][0], hv.y, w0.y);
                ffma2(a[r][1], hv.x, w1.x); ffma2(a[r][1], hv.y, w1.y);
                ffma2(a[r][2], hv.x, w2.x); ffma2(a[r][2], hv.y, w2.y);
                ffma2(a[r][3], hv.x, w3.x); ffma2(a[r][3], hv.y, w3.y);
            }
        }
        float h0v[4];
        #pragma unroll
        for (int r = 0; r < 4; ++r) {
            float gi = redu(a[r][0]);
            float gf = redu(a[r][1]);
            float gg_ = redu(a[r][2]);
            float go = redu(a[r][3]);
            c0[r]  = sigmf(gf) * c0[r] + sigmf(gi) * tanhfa(gg_);
            h0v[r] = sigmf(go) * tanhfa(c0[r]);
        }
        __syncwarp();
        #pragma unroll
        for (int r = 0; r < 4; ++r) ((float*)hb[r])[lane] = h0v[r];
        __syncwarp();

        // ---- layer 1 ----
        #pragma unroll
        for (int r = 0; r < 4; ++r) {
            a[r][0] = binit1[0]; a[r][1] = binit1[1];
            a[r][2] = binit1[2]; a[r][3] = binit1[3];
        }
        #pragma unroll
        for (int hp2 = 0; hp2 < 16; ++hp2) {
            ulonglong2 w0 = Wcq[hp2 * 128 + lane];
            ulonglong2 w1 = Wcq[hp2 * 128 + lane + 32];
            ulonglong2 w2 = Wcq[hp2 * 128 + lane + 64];
            ulonglong2 w3 = Wcq[hp2 * 128 + lane + 96];
            #pragma unroll
            for (int r = 0; r < 4; ++r) {
                ulonglong2 hv = ((const ulonglong2*)hb[r])[hp2];
                ffma2(a[r][0], hv.x, w0.x); ffma2(a[r][0], hv.y, w0.y);
                ffma2(a[r][1], hv.x, w1.x); ffma2(a[r][1], hv.y, w1.y);
                ffma2(a[r][2], hv.x, w2.x); ffma2(a[r][2], hv.y, w2.y);
                ffma2(a[r][3], hv.x, w3.x); ffma2(a[r][3], hv.y, w3.y);
            }
        }
        #pragma unroll
        for (int r = 0; r < 4; ++r) {
            float gi = redu(a[r][0]);
            float gf = redu(a[r][1]);
            float gg_ = redu(a[r][2]);
            float go = redu(a[r][3]);
            c1[r]  = sigmf(gf) * c1[r] + sigmf(gi) * tanhfa(gg_);
            h1v[r] = sigmf(go) * tanhfa(c1[r]);
        }
        __syncwarp();
        #pragma unroll
        for (int r = 0; r < 4; ++r) ((float*)hb[r])[32 + lane] = h1v[r];
        __syncwarp();
    }

    #pragma unroll
    for (int r = 0; r < 4; ++r)
        g_comb[(size_t)(b0 + wg * 4 + r) * 1024 + f * 32 + lane] = h1v[r];
}

// ---------------------------------------------------------------------------
// Kernel 3: gaussian head. Block per b.
// ---------------------------------------------------------------------------
__global__ __launch_bounds__(128) void k_head(
    const float* __restrict__ mu_w, const float* __restrict__ mu_b,
    const float* __restrict__ lv_w, const float* __restrict__ lv_b,
    float* __restrict__ out)
{
    __shared__ float smu[4], slv[4];
    const int tid = threadIdx.x, b = blockIdx.x;
    float am = 0.0f, al = 0.0f;
    for (int i = tid; i < 1024; i += 128) {
        float v = g_comb[(size_t)b * 1024 + i];
        am += v * mu_w[i];
        al += v * lv_w[i];
    }
    #pragma unroll
    for (int s = 16; s > 0; s >>= 1) {
        am += __shfl_xor_sync(0xffffffffu, am, s);
        al += __shfl_xor_sync(0xffffffffu, al, s);
    }
    const int wg = tid >> 5, lane = tid & 31;
    if (lane == 0) { smu[wg] = am; slv[wg] = al; }
    __syncthreads();
    if (tid == 0) {
        float mu = smu[0] + smu[1] + smu[2] + smu[3] + mu_b[0];
        float lv = slv[0] + slv[1] + slv[2] + slv[3] + lv_b[0];
        float sg = expf(0.5f * lv);
        out[b]       = mu - 1.96f * sg;
        out[128 + b] = mu;
        out[256 + b] = mu + 1.96f * sg;
        out[384 + b] = lv;
    }
}

// ---------------------------------------------------------------------------
extern "C" void kernel_launch(void* const* d_in, const int* in_sizes, int n_in,
                              void* d_out, int out_size)
{
    const float* x      = (const float*)d_in[0];
    const float* conv_w = (const float*)d_in[1];
    const float* conv_b = (const float*)d_in[2];
    const float* fc1_w  = (const float*)d_in[3];
    const float* fc1_b  = (const float*)d_in[4];
    const float* w_ih0  = (const float*)d_in[5];
    const float* w_ih1  = (const float*)d_in[6];
    const float* w_hh   = (const float*)d_in[7];
    const float* b_lstm = (const float*)d_in[8];
    const float* mu_w   = (const float*)d_in[9];
    const float* mu_b   = (const float*)d_in[10];
    const float* lv_w   = (const float*)d_in[11];
    const float* lv_b   = (const float*)d_in[12];
    float* out = (float*)d_out;

    const int SM1 = (33344 + 16640 + 2048 + 2112 + 768 + 256 + 32) * (int)sizeof(float); // 220,800 B
    const int SM2 = 9408 * (int)sizeof(ull);                                             //  75,264 B

    cudaFuncSetAttribute(k_convfc, cudaFuncAttributeMaxDynamicSharedMemorySize, SM1);
    cudaFuncSetAttribute(k_lstm,   cudaFuncAttributeMaxDynamicSharedMemorySize, SM2);

    k_convfc<<<128, 512, SM1>>>(x, conv_w, conv_b, fc1_w, fc1_b);
    k_lstm<<<128, 256, SM2>>>(w_ih0, w_ih1, w_hh, b_lstm);
    k_head<<<128, 128>>>(mu_w, mu_b, lv_w, lv_b, out);
}